// round 8
// baseline (speedup 1.0000x reference)
#include <cuda_runtime.h>

#define NB 8
#define CB 8
#define HH 256
#define OH 128
#define HWP 16384   // 128*128

// ---------------- scratch (device globals; no allocation allowed) ----------
__device__ float g_D[NB * CB * OH * OH];        // blur - y     (4 MB)
__device__ float g_Gp[16 * NB * CB * 128];      // partial G: [band16][n][c][128] (512 KB)

__device__ __forceinline__ int refl(int q) {
    // jnp.pad mode='reflect' (no edge duplication), pad=5 < 256 so one fold is enough
    if (q < 0) q = -q;
    if (q >= HH) q = 2 * HH - 2 - q;
    return q;
}

// ============================================================================
// Kernel A: D = blur(x; k, stride2, reflect pad 5) - y
// grid (band=8, c=8, n=8), 256 threads. band = 16 output rows.
// ============================================================================
__global__ __launch_bounds__(256) void blur_kernel(const float* __restrict__ x,
                                                   const float* __restrict__ y,
                                                   const float* __restrict__ kk)
{
    const int band = blockIdx.x;          // 16 pi rows
    const int c = blockIdx.y, n = blockIdx.z;
    __shared__ float sx[41][268];         // rows 2*pi0 .. 2*pi0+40, cols 0..265 (padded)
    __shared__ float sk[121];

    const float* xc = x + (size_t)(n * CB + c) * HH * HH;
    const int pi0 = band * 16;

    for (int t = threadIdx.x; t < 121; t += 256)
        sk[t] = kk[(n * CB + c) * 121 + t];

    for (int idx = threadIdx.x; idx < 41 * 266; idx += 256) {
        int dr = idx / 266, cc = idx - dr * 266;
        sx[dr][cc] = xc[refl(2 * pi0 + dr - 5) * HH + refl(cc - 5)];
    }
    __syncthreads();

    const int pj = threadIdx.x & 127;
    for (int rp = (threadIdx.x >> 7); rp < 16; rp += 2) {
        float acc = 0.f;
        #pragma unroll
        for (int ki = 0; ki < 11; ki++) {
            // &sx[r][2*pj] is 8B aligned: row stride 268 floats (even), 2*pj even
            const float2* row2 = reinterpret_cast<const float2*>(&sx[2 * rp + ki][2 * pj]);
            const float* skr = &sk[ki * 11];
            #pragma unroll
            for (int h = 0; h < 5; h++) {
                float2 v = row2[h];
                acc += v.x * skr[2 * h] + v.y * skr[2 * h + 1];
            }
            acc += sx[2 * rp + ki][2 * pj + 10] * skr[10];
        }
        const int pi = pi0 + rp;
        const int o = ((n * CB + c) * OH + pi) * OH + pj;
        g_D[o] = acc - y[o];
    }
}

// ============================================================================
// Kernel B: partial G[n,k,c] over an 8-row band of pi.
//   R[n, p, c] = D_flat[n, p*8 + c]  ->  channel = pi>>4,
//   spatial = (pi&15)*1024 + pj*8 + c
// grid (band=16, c=8, n=8), 128 threads (one per k=ki*11+kj, 121 active).
// ============================================================================
__global__ __launch_bounds__(128) void grad_kernel(const float* __restrict__ x)
{
    const int band = blockIdx.x;          // 8 pi rows
    const int c = blockIdx.y, n = blockIdx.z;
    __shared__ float sx[25][268];         // rows 2*pi0 .. 2*pi0+24
    __shared__ float sR[8][128];

    const float* xc = x + (size_t)(n * CB + c) * HH * HH;
    const int pi0 = band * 8;

    for (int idx = threadIdx.x; idx < 25 * 266; idx += 128) {
        int dr = idx / 266, cc = idx - dr * 266;
        sx[dr][cc] = xc[refl(2 * pi0 + dr - 5) * HH + refl(cc - 5)];
    }
    for (int idx = threadIdx.x; idx < 8 * 128; idx += 128) {
        int dpi = idx >> 7, pj = idx & 127;
        int pi = pi0 + dpi;
        sR[dpi][pj] = g_D[(size_t)(n * CB + (pi >> 4)) * HWP
                          + (pi & 15) * 1024 + pj * 8 + c];
    }
    __syncthreads();

    const int k = threadIdx.x;
    if (k < 121) {
        const int ki = k / 11, kj = k - ki * 11;
        float acc = 0.f;
        #pragma unroll
        for (int dpi = 0; dpi < 8; dpi++) {
            const float* xrow = &sx[2 * dpi + ki][kj];
            const float* rrow = sR[dpi];
            #pragma unroll 16
            for (int pj = 0; pj < 128; pj++)
                acc += xrow[2 * pj] * rrow[pj];
        }
        g_Gp[(((size_t)band * NB + n) * CB + c) * 128 + k] = acc;
    }
}

// ============================================================================
// Kernel C: assemble G_K, run the whole pronet (9 convs) in smem, normalize.
// grid = 8 blocks (one per n), 256 threads.
// ============================================================================
struct PronetArgs {
    const float* kin;
    const float* gamma;   // may be null -> 1.0
    const float* w[9];
    const float* b[9];
    float* out;
};

__device__ void conv_sm(const float* __restrict__ in, float* __restrict__ out,
                        const float* __restrict__ wg, const float* __restrict__ bg,
                        bool do_relu, int tid, float* sw, float* sb)
{
    __syncthreads();                         // prior users of sw / writers of 'in' done
    for (int i = tid; i < 576; i += 256) sw[i] = wg[i];
    if (tid < 8) sb[tid] = bg[tid];
    __syncthreads();

    for (int f = tid; f < 968; f += 256) {
        int cc = f / 121, rem = f - cc * 121;
        int i = rem / 11, j = rem - i * 11;
        float acc = sb[cc];
        const float* wp = sw + cc * 72;
        #pragma unroll
        for (int ci = 0; ci < 8; ci++) {
            #pragma unroll
            for (int dy = 0; dy < 3; dy++) {
                int yy = i + dy - 1;
                if (yy < 0 || yy > 10) continue;
                #pragma unroll
                for (int dx = 0; dx < 3; dx++) {
                    int xx = j + dx - 1;
                    if (xx < 0 || xx > 10) continue;
                    acc += in[ci * 121 + yy * 11 + xx] * wp[ci * 9 + dy * 3 + dx];
                }
            }
        }
        out[f] = do_relu ? fmaxf(acc, 0.f) : acc;
    }
    __syncthreads();
}

__global__ __launch_bounds__(256) void pronet_kernel(PronetArgs a)
{
    const int n = blockIdx.x;
    __shared__ float sg[968], sx[968], st[968], su[968];
    __shared__ float sw[576], sb[8], ssum[8];
    const int tid = threadIdx.x;

    const float gam = a.gamma ? a.gamma[0] : 1.0f;
    const float scale = gam * (0.1f / 16384.f);

    // G_K[n, f] = k[n, f] - scale * G_flat[n, f],  G_flat[f] -> (k=f>>3, c=f&7)
    for (int f = tid; f < 968; f += 256) {
        float s = 0.f;
        #pragma unroll
        for (int bnd = 0; bnd < 16; bnd++)
            s += g_Gp[(((size_t)bnd * NB + n) * CB + (f & 7)) * 128 + (f >> 3)];
        float gk = a.kin[n * 968 + f] - scale * s;
        sg[f] = gk;
        sx[f] = gk;
    }

    // 4 residual blocks: x = relu(x + 0.1 * conv(relu(conv(x))))
    for (int s = 0; s < 4; s++) {
        conv_sm(sx, st, a.w[2 * s],     a.b[2 * s],     true,  tid, sw, sb);
        conv_sm(st, su, a.w[2 * s + 1], a.b[2 * s + 1], false, tid, sw, sb);
        for (int f = tid; f < 968; f += 256)
            sx[f] = fmaxf(sx[f] + 0.1f * su[f], 0.f);
    }
    // final: K = relu(g + 0.1 * conv(x4))   (outer relu idempotent)
    conv_sm(sx, su, a.w[8], a.b[8], false, tid, sw, sb);
    for (int f = tid; f < 968; f += 256)
        st[f] = fmaxf(sg[f] + 0.1f * su[f], 0.f);
    __syncthreads();

    // per-channel sums (warp per channel)
    const int wid = tid >> 5, lane = tid & 31;
    if (wid < 8) {
        float s = 0.f;
        for (int e = lane; e < 121; e += 32) s += st[wid * 121 + e];
        #pragma unroll
        for (int o = 16; o; o >>= 1) s += __shfl_xor_sync(0xffffffffu, s, o);
        if (lane == 0) ssum[wid] = s;
    }
    __syncthreads();

    for (int f = tid; f < 968; f += 256)
        a.out[n * 968 + f] = st[f] / ssum[f / 121];
}

// ============================================================================
extern "C" void kernel_launch(void* const* d_in, const int* in_sizes, int n_in,
                              void* d_out, int out_size)
{
    const float* x = nullptr;
    const float* y = nullptr;
    const float* kk = nullptr;
    const float* w[9] = {};
    const float* b[9] = {};
    const float* scalars[4] = {};
    int nw = 0, nbias = 0, nsc = 0;

    for (int i = 0; i < n_in; i++) {
        int s = in_sizes[i];
        if (s == NB * CB * HH * HH)            x = (const float*)d_in[i];
        else if (s == NB * CB * OH * OH)       y = (const float*)d_in[i];
        else if (s == NB * CB * 121)           kk = (const float*)d_in[i];
        else if (s == 576 && nw < 9)           w[nw++] = (const float*)d_in[i];
        else if (s == 8 && nbias < 9)          b[nbias++] = (const float*)d_in[i];
        else if (s == 1 && nsc < 4)            scalars[nsc++] = (const float*)d_in[i];
    }
    // inputs arrive in setup order: ... sf (int, size 1), gamma (float, size 1) ...
    const float* gamma = (nsc >= 2) ? scalars[1] : (nsc == 1 ? scalars[0] : nullptr);

    blur_kernel<<<dim3(8, 8, 8), 256>>>(x, y, kk);
    grad_kernel<<<dim3(16, 8, 8), 128>>>(x);

    PronetArgs a;
    a.kin = kk;
    a.gamma = gamma;
    for (int i = 0; i < 9; i++) { a.w[i] = w[i]; a.b[i] = b[i]; }
    a.out = (float*)d_out;
    pronet_kernel<<<8, 256>>>(a);
}

// round 9
// speedup vs baseline: 1.0007x; 1.0007x over previous
#include <cuda_runtime.h>

#define NB 8
#define CB 8
#define HH 256
#define OH 128
#define HWP 16384   // 128*128

// ---------------- scratch (device globals; no allocation allowed) ----------
__device__ float g_D[NB * CB * OH * OH];        // blur - y     (4 MB)
__device__ float g_Gp[16 * NB * CB * 128];      // partial G: [band16][n][c][128] (512 KB)

__device__ __forceinline__ int refl(int q) {
    // jnp.pad mode='reflect' (no edge duplication), pad=5 < 256 so one fold is enough
    if (q < 0) q = -q;
    if (q >= HH) q = 2 * HH - 2 - q;
    return q;
}

// ============================================================================
// Kernel A: D = blur(x; k, stride2, reflect pad 5) - y
// grid (band=8, c=8, n=8), 256 threads. band = 16 output rows.
// ============================================================================
__global__ __launch_bounds__(256) void blur_kernel(const float* __restrict__ x,
                                                   const float* __restrict__ y,
                                                   const float* __restrict__ kk)
{
    const int band = blockIdx.x;          // 16 pi rows
    const int c = blockIdx.y, n = blockIdx.z;
    __shared__ float sx[41][268];         // rows 2*pi0 .. 2*pi0+40, cols 0..265 (padded)
    __shared__ float sk[121];

    const float* xc = x + (size_t)(n * CB + c) * HH * HH;
    const int pi0 = band * 16;

    for (int t = threadIdx.x; t < 121; t += 256)
        sk[t] = kk[(n * CB + c) * 121 + t];

    for (int idx = threadIdx.x; idx < 41 * 266; idx += 256) {
        int dr = idx / 266, cc = idx - dr * 266;
        sx[dr][cc] = xc[refl(2 * pi0 + dr - 5) * HH + refl(cc - 5)];
    }
    __syncthreads();

    const int pj = threadIdx.x & 127;
    for (int rp = (threadIdx.x >> 7); rp < 16; rp += 2) {
        float acc = 0.f;
        #pragma unroll
        for (int ki = 0; ki < 11; ki++) {
            // &sx[r][2*pj] is 8B aligned: row stride 268 floats (even), 2*pj even
            const float2* row2 = reinterpret_cast<const float2*>(&sx[2 * rp + ki][2 * pj]);
            const float* skr = &sk[ki * 11];
            #pragma unroll
            for (int h = 0; h < 5; h++) {
                float2 v = row2[h];
                acc += v.x * skr[2 * h] + v.y * skr[2 * h + 1];
            }
            acc += sx[2 * rp + ki][2 * pj + 10] * skr[10];
        }
        const int pi = pi0 + rp;
        const int o = ((n * CB + c) * OH + pi) * OH + pj;
        g_D[o] = acc - y[o];
    }
}

// ============================================================================
// Kernel B: partial G[n,k,c] over an 8-row band of pi.
//   R[n, p, c] = D_flat[n, p*8 + c]  ->  channel = pi>>4,
//   spatial = (pi&15)*1024 + pj*8 + c
// grid (band=16, c=8, n=8), 128 threads (one per k=ki*11+kj, 121 active).
// ============================================================================
__global__ __launch_bounds__(128) void grad_kernel(const float* __restrict__ x)
{
    const int band = blockIdx.x;          // 8 pi rows
    const int c = blockIdx.y, n = blockIdx.z;
    __shared__ float sx[25][268];         // rows 2*pi0 .. 2*pi0+24
    __shared__ float sR[8][128];

    const float* xc = x + (size_t)(n * CB + c) * HH * HH;
    const int pi0 = band * 8;

    for (int idx = threadIdx.x; idx < 25 * 266; idx += 128) {
        int dr = idx / 266, cc = idx - dr * 266;
        sx[dr][cc] = xc[refl(2 * pi0 + dr - 5) * HH + refl(cc - 5)];
    }
    for (int idx = threadIdx.x; idx < 8 * 128; idx += 128) {
        int dpi = idx >> 7, pj = idx & 127;
        int pi = pi0 + dpi;
        sR[dpi][pj] = g_D[(size_t)(n * CB + (pi >> 4)) * HWP
                          + (pi & 15) * 1024 + pj * 8 + c];
    }
    __syncthreads();

    const int k = threadIdx.x;
    if (k < 121) {
        const int ki = k / 11, kj = k - ki * 11;
        float acc = 0.f;
        #pragma unroll
        for (int dpi = 0; dpi < 8; dpi++) {
            const float* xrow = &sx[2 * dpi + ki][kj];
            const float* rrow = sR[dpi];
            #pragma unroll 16
            for (int pj = 0; pj < 128; pj++)
                acc += xrow[2 * pj] * rrow[pj];
        }
        g_Gp[(((size_t)band * NB + n) * CB + c) * 128 + k] = acc;
    }
}

// ============================================================================
// Kernel C: assemble G_K, run the whole pronet (9 convs) in smem, normalize.
// grid = 8 blocks (one per n), 256 threads.
// ============================================================================
struct PronetArgs {
    const float* kin;
    const float* gamma;   // may be null -> 1.0
    const float* w[9];
    const float* b[9];
    float* out;
};

__device__ void conv_sm(const float* __restrict__ in, float* __restrict__ out,
                        const float* __restrict__ wg, const float* __restrict__ bg,
                        bool do_relu, int tid, float* sw, float* sb)
{
    __syncthreads();                         // prior users of sw / writers of 'in' done
    for (int i = tid; i < 576; i += 256) sw[i] = wg[i];
    if (tid < 8) sb[tid] = bg[tid];
    __syncthreads();

    for (int f = tid; f < 968; f += 256) {
        int cc = f / 121, rem = f - cc * 121;
        int i = rem / 11, j = rem - i * 11;
        float acc = sb[cc];
        const float* wp = sw + cc * 72;
        #pragma unroll
        for (int ci = 0; ci < 8; ci++) {
            #pragma unroll
            for (int dy = 0; dy < 3; dy++) {
                int yy = i + dy - 1;
                if (yy < 0 || yy > 10) continue;
                #pragma unroll
                for (int dx = 0; dx < 3; dx++) {
                    int xx = j + dx - 1;
                    if (xx < 0 || xx > 10) continue;
                    acc += in[ci * 121 + yy * 11 + xx] * wp[ci * 9 + dy * 3 + dx];
                }
            }
        }
        out[f] = do_relu ? fmaxf(acc, 0.f) : acc;
    }
    __syncthreads();
}

__global__ __launch_bounds__(256) void pronet_kernel(PronetArgs a)
{
    const int n = blockIdx.x;
    __shared__ float sg[968], sx[968], st[968], su[968];
    __shared__ float sw[576], sb[8], ssum[8];
    const int tid = threadIdx.x;

    const float gam = a.gamma ? a.gamma[0] : 1.0f;
    const float scale = gam * (0.1f / 16384.f);

    // G_K[n, f] = k[n, f] - scale * G_flat[n, f],  G_flat[f] -> (k=f>>3, c=f&7)
    for (int f = tid; f < 968; f += 256) {
        float s = 0.f;
        #pragma unroll
        for (int bnd = 0; bnd < 16; bnd++)
            s += g_Gp[(((size_t)bnd * NB + n) * CB + (f & 7)) * 128 + (f >> 3)];
        float gk = a.kin[n * 968 + f] - scale * s;
        sg[f] = gk;
        sx[f] = gk;
    }

    // 4 residual blocks: x = relu(x + 0.1 * conv(relu(conv(x))))
    for (int s = 0; s < 4; s++) {
        conv_sm(sx, st, a.w[2 * s],     a.b[2 * s],     true,  tid, sw, sb);
        conv_sm(st, su, a.w[2 * s + 1], a.b[2 * s + 1], false, tid, sw, sb);
        for (int f = tid; f < 968; f += 256)
            sx[f] = fmaxf(sx[f] + 0.1f * su[f], 0.f);
    }
    // final: K = relu(g + 0.1 * conv(x4))   (outer relu idempotent)
    conv_sm(sx, su, a.w[8], a.b[8], false, tid, sw, sb);
    for (int f = tid; f < 968; f += 256)
        st[f] = fmaxf(sg[f] + 0.1f * su[f], 0.f);
    __syncthreads();

    // per-channel sums (warp per channel)
    const int wid = tid >> 5, lane = tid & 31;
    if (wid < 8) {
        float s = 0.f;
        for (int e = lane; e < 121; e += 32) s += st[wid * 121 + e];
        #pragma unroll
        for (int o = 16; o; o >>= 1) s += __shfl_xor_sync(0xffffffffu, s, o);
        if (lane == 0) ssum[wid] = s;
    }
    __syncthreads();

    for (int f = tid; f < 968; f += 256)
        a.out[n * 968 + f] = st[f] / ssum[f / 121];
}

// ============================================================================
extern "C" void kernel_launch(void* const* d_in, const int* in_sizes, int n_in,
                              void* d_out, int out_size)
{
    const float* x = nullptr;
    const float* y = nullptr;
    const float* kk = nullptr;
    const float* w[9] = {};
    const float* b[9] = {};
    const float* scalars[4] = {};
    int nw = 0, nbias = 0, nsc = 0;

    for (int i = 0; i < n_in; i++) {
        int s = in_sizes[i];
        if (s == NB * CB * HH * HH)            x = (const float*)d_in[i];
        else if (s == NB * CB * OH * OH)       y = (const float*)d_in[i];
        else if (s == NB * CB * 121)           kk = (const float*)d_in[i];
        else if (s == 576 && nw < 9)           w[nw++] = (const float*)d_in[i];
        else if (s == 8 && nbias < 9)          b[nbias++] = (const float*)d_in[i];
        else if (s == 1 && nsc < 4)            scalars[nsc++] = (const float*)d_in[i];
    }
    // inputs arrive in setup order: ... sf (int, size 1), gamma (float, size 1) ...
    const float* gamma = (nsc >= 2) ? scalars[1] : (nsc == 1 ? scalars[0] : nullptr);

    blur_kernel<<<dim3(8, 8, 8), 256>>>(x, y, kk);
    grad_kernel<<<dim3(16, 8, 8), 128>>>(x);

    PronetArgs a;
    a.kin = kk;
    a.gamma = gamma;
    for (int i = 0; i < 9; i++) { a.w[i] = w[i]; a.b[i] = b[i]; }
    a.out = (float*)d_out;
    pronet_kernel<<<8, 256>>>(a);
}

// round 10
// speedup vs baseline: 1.0054x; 1.0047x over previous
#include <cuda_runtime.h>

#define NB 8
#define CB 8
#define HH 256
#define OH 128
#define HWP 16384   // 128*128

// ---------------- scratch (device globals; no allocation allowed) ----------
__device__ float g_D[NB * CB * OH * OH];        // blur - y     (4 MB)
__device__ float g_Gp[16 * NB * CB * 128];      // partial G: [band16][n][c][128] (512 KB)

__device__ __forceinline__ int refl(int q) {
    // jnp.pad mode='reflect' (no edge duplication), pad=5 < 256 so one fold is enough
    if (q < 0) q = -q;
    if (q >= HH) q = 2 * HH - 2 - q;
    return q;
}

// ============================================================================
// Kernel A: D = blur(x; k, stride2, reflect pad 5) - y
// grid (band=8, c=8, n=8), 256 threads. band = 16 output rows.
// ============================================================================
__global__ __launch_bounds__(256) void blur_kernel(const float* __restrict__ x,
                                                   const float* __restrict__ y,
                                                   const float* __restrict__ kk)
{
    const int band = blockIdx.x;          // 16 pi rows
    const int c = blockIdx.y, n = blockIdx.z;
    __shared__ float sx[41][268];         // rows 2*pi0 .. 2*pi0+40, cols 0..265 (padded)
    __shared__ float sk[121];

    const float* xc = x + (size_t)(n * CB + c) * HH * HH;
    const int pi0 = band * 16;

    for (int t = threadIdx.x; t < 121; t += 256)
        sk[t] = kk[(n * CB + c) * 121 + t];

    for (int idx = threadIdx.x; idx < 41 * 266; idx += 256) {
        int dr = idx / 266, cc = idx - dr * 266;
        sx[dr][cc] = xc[refl(2 * pi0 + dr - 5) * HH + refl(cc - 5)];
    }
    __syncthreads();

    const int pj = threadIdx.x & 127;
    for (int rp = (threadIdx.x >> 7); rp < 16; rp += 2) {
        float acc = 0.f;
        #pragma unroll
        for (int ki = 0; ki < 11; ki++) {
            // &sx[r][2*pj] is 8B aligned: row stride 268 floats (even), 2*pj even
            const float2* row2 = reinterpret_cast<const float2*>(&sx[2 * rp + ki][2 * pj]);
            const float* skr = &sk[ki * 11];
            #pragma unroll
            for (int h = 0; h < 5; h++) {
                float2 v = row2[h];
                acc += v.x * skr[2 * h] + v.y * skr[2 * h + 1];
            }
            acc += sx[2 * rp + ki][2 * pj + 10] * skr[10];
        }
        const int pi = pi0 + rp;
        const int o = ((n * CB + c) * OH + pi) * OH + pj;
        g_D[o] = acc - y[o];
    }
}

// ============================================================================
// Kernel B: partial G[n,k,c] over an 8-row band of pi.
//   R[n, p, c] = D_flat[n, p*8 + c]  ->  channel = pi>>4,
//   spatial = (pi&15)*1024 + pj*8 + c
// grid (band=16, c=8, n=8), 128 threads (one per k=ki*11+kj, 121 active).
// ============================================================================
__global__ __launch_bounds__(128) void grad_kernel(const float* __restrict__ x)
{
    const int band = blockIdx.x;          // 8 pi rows
    const int c = blockIdx.y, n = blockIdx.z;
    __shared__ float sx[25][268];         // rows 2*pi0 .. 2*pi0+24
    __shared__ float sR[8][128];

    const float* xc = x + (size_t)(n * CB + c) * HH * HH;
    const int pi0 = band * 8;

    for (int idx = threadIdx.x; idx < 25 * 266; idx += 128) {
        int dr = idx / 266, cc = idx - dr * 266;
        sx[dr][cc] = xc[refl(2 * pi0 + dr - 5) * HH + refl(cc - 5)];
    }
    for (int idx = threadIdx.x; idx < 8 * 128; idx += 128) {
        int dpi = idx >> 7, pj = idx & 127;
        int pi = pi0 + dpi;
        sR[dpi][pj] = g_D[(size_t)(n * CB + (pi >> 4)) * HWP
                          + (pi & 15) * 1024 + pj * 8 + c];
    }
    __syncthreads();

    const int k = threadIdx.x;
    if (k < 121) {
        const int ki = k / 11, kj = k - ki * 11;
        float acc = 0.f;
        #pragma unroll
        for (int dpi = 0; dpi < 8; dpi++) {
            const float* xrow = &sx[2 * dpi + ki][kj];
            const float* rrow = sR[dpi];
            #pragma unroll 16
            for (int pj = 0; pj < 128; pj++)
                acc += xrow[2 * pj] * rrow[pj];
        }
        g_Gp[(((size_t)band * NB + n) * CB + c) * 128 + k] = acc;
    }
}

// ============================================================================
// Kernel C: assemble G_K, run the whole pronet (9 convs) in smem, normalize.
// grid = 8 blocks (one per n), 256 threads.
// ============================================================================
struct PronetArgs {
    const float* kin;
    const float* gamma;   // may be null -> 1.0
    const float* w[9];
    const float* b[9];
    float* out;
};

__device__ void conv_sm(const float* __restrict__ in, float* __restrict__ out,
                        const float* __restrict__ wg, const float* __restrict__ bg,
                        bool do_relu, int tid, float* sw, float* sb)
{
    __syncthreads();                         // prior users of sw / writers of 'in' done
    for (int i = tid; i < 576; i += 256) sw[i] = wg[i];
    if (tid < 8) sb[tid] = bg[tid];
    __syncthreads();

    for (int f = tid; f < 968; f += 256) {
        int cc = f / 121, rem = f - cc * 121;
        int i = rem / 11, j = rem - i * 11;
        float acc = sb[cc];
        const float* wp = sw + cc * 72;
        #pragma unroll
        for (int ci = 0; ci < 8; ci++) {
            #pragma unroll
            for (int dy = 0; dy < 3; dy++) {
                int yy = i + dy - 1;
                if (yy < 0 || yy > 10) continue;
                #pragma unroll
                for (int dx = 0; dx < 3; dx++) {
                    int xx = j + dx - 1;
                    if (xx < 0 || xx > 10) continue;
                    acc += in[ci * 121 + yy * 11 + xx] * wp[ci * 9 + dy * 3 + dx];
                }
            }
        }
        out[f] = do_relu ? fmaxf(acc, 0.f) : acc;
    }
    __syncthreads();
}

__global__ __launch_bounds__(256) void pronet_kernel(PronetArgs a)
{
    const int n = blockIdx.x;
    __shared__ float sg[968], sx[968], st[968], su[968];
    __shared__ float sw[576], sb[8], ssum[8];
    const int tid = threadIdx.x;

    const float gam = a.gamma ? a.gamma[0] : 1.0f;
    const float scale = gam * (0.1f / 16384.f);

    // G_K[n, f] = k[n, f] - scale * G_flat[n, f],  G_flat[f] -> (k=f>>3, c=f&7)
    for (int f = tid; f < 968; f += 256) {
        float s = 0.f;
        #pragma unroll
        for (int bnd = 0; bnd < 16; bnd++)
            s += g_Gp[(((size_t)bnd * NB + n) * CB + (f & 7)) * 128 + (f >> 3)];
        float gk = a.kin[n * 968 + f] - scale * s;
        sg[f] = gk;
        sx[f] = gk;
    }

    // 4 residual blocks: x = relu(x + 0.1 * conv(relu(conv(x))))
    for (int s = 0; s < 4; s++) {
        conv_sm(sx, st, a.w[2 * s],     a.b[2 * s],     true,  tid, sw, sb);
        conv_sm(st, su, a.w[2 * s + 1], a.b[2 * s + 1], false, tid, sw, sb);
        for (int f = tid; f < 968; f += 256)
            sx[f] = fmaxf(sx[f] + 0.1f * su[f], 0.f);
    }
    // final: K = relu(g + 0.1 * conv(x4))   (outer relu idempotent)
    conv_sm(sx, su, a.w[8], a.b[8], false, tid, sw, sb);
    for (int f = tid; f < 968; f += 256)
        st[f] = fmaxf(sg[f] + 0.1f * su[f], 0.f);
    __syncthreads();

    // per-channel sums (warp per channel)
    const int wid = tid >> 5, lane = tid & 31;
    if (wid < 8) {
        float s = 0.f;
        for (int e = lane; e < 121; e += 32) s += st[wid * 121 + e];
        #pragma unroll
        for (int o = 16; o; o >>= 1) s += __shfl_xor_sync(0xffffffffu, s, o);
        if (lane == 0) ssum[wid] = s;
    }
    __syncthreads();

    for (int f = tid; f < 968; f += 256)
        a.out[n * 968 + f] = st[f] / ssum[f / 121];
}

// ============================================================================
extern "C" void kernel_launch(void* const* d_in, const int* in_sizes, int n_in,
                              void* d_out, int out_size)
{
    const float* x = nullptr;
    const float* y = nullptr;
    const float* kk = nullptr;
    const float* w[9] = {};
    const float* b[9] = {};
    const float* scalars[4] = {};
    int nw = 0, nbias = 0, nsc = 0;

    for (int i = 0; i < n_in; i++) {
        int s = in_sizes[i];
        if (s == NB * CB * HH * HH)            x = (const float*)d_in[i];
        else if (s == NB * CB * OH * OH)       y = (const float*)d_in[i];
        else if (s == NB * CB * 121)           kk = (const float*)d_in[i];
        else if (s == 576 && nw < 9)           w[nw++] = (const float*)d_in[i];
        else if (s == 8 && nbias < 9)          b[nbias++] = (const float*)d_in[i];
        else if (s == 1 && nsc < 4)            scalars[nsc++] = (const float*)d_in[i];
    }
    // inputs arrive in setup order: ... sf (int, size 1), gamma (float, size 1) ...
    const float* gamma = (nsc >= 2) ? scalars[1] : (nsc == 1 ? scalars[0] : nullptr);

    blur_kernel<<<dim3(8, 8, 8), 256>>>(x, y, kk);
    grad_kernel<<<dim3(16, 8, 8), 128>>>(x);

    PronetArgs a;
    a.kin = kk;
    a.gamma = gamma;
    for (int i = 0; i < 9; i++) { a.w[i] = w[i]; a.b[i] = b[i]; }
    a.out = (float*)d_out;
    pronet_kernel<<<8, 256>>>(a);
}